// round 5
// baseline (speedup 1.0000x reference)
#include <cuda_runtime.h>
#include <cuda_fp16.h>
#include <cstdint>

#define DEV_INLINE __device__ __forceinline__

constexpr int NN = 8192;   // nodes
constexpr int DF = 256;    // feature dim
constexpr float YSCALE = 4096.f;   // exact pow2: keeps Y out of fp16 subnormals

// ---------------- intermediates (static device globals; no runtime alloc) ----
__device__ float  g_inv_deg[NN];
__device__ __half g_ysTh[(size_t)DF * NN];   // [d][j] = fp16( YSCALE*inv_j*(xW)[j][d] )

// ============================================================================
// helpers (baseline sm_103 ISA only: cp.async, ldmatrix, mma.sync)
// ============================================================================
DEV_INLINE uint32_t smem_u32(const void* p) {
    uint32_t a;
    asm("{ .reg .u64 t; cvta.to.shared.u64 t, %1; cvt.u32.u64 %0, t; }" : "=r"(a) : "l"(p));
    return a;
}
DEV_INLINE void cp16(uint32_t saddr, const void* g) {
    asm volatile("cp.async.cg.shared.global [%0], [%1], 16;" :: "r"(saddr), "l"(g));
}
DEV_INLINE void cp_commit() { asm volatile("cp.async.commit_group;"); }
template <int N> DEV_INLINE void cp_wait() { asm volatile("cp.async.wait_group %0;" :: "n"(N)); }

DEV_INLINE void ldsm4(uint32_t* d, uint32_t addr) {
    asm volatile("ldmatrix.sync.aligned.m8n8.x4.shared.b16 {%0,%1,%2,%3}, [%4];"
                 : "=r"(d[0]), "=r"(d[1]), "=r"(d[2]), "=r"(d[3]) : "r"(addr));
}
// load float2 from smem, pack to fp16x2 {lo=x (k even), hi=y (k odd)}
DEV_INLINE uint32_t lds_cvt(uint32_t addr) {
    float2 v;
    asm volatile("ld.shared.v2.f32 {%0,%1}, [%2];" : "=f"(v.x), "=f"(v.y) : "r"(addr));
    uint32_t d;
    asm("cvt.rn.f16x2.f32 %0, %1, %2;" : "=r"(d) : "f"(v.y), "f"(v.x));
    return d;
}
DEV_INLINE void mma_f16(float* c, const uint32_t* a, const uint32_t* b) {
    asm volatile(
        "mma.sync.aligned.m16n8k16.row.col.f32.f16.f16.f32 "
        "{%0,%1,%2,%3}, {%4,%5,%6,%7}, {%8,%9}, {%0,%1,%2,%3};"
        : "+f"(c[0]), "+f"(c[1]), "+f"(c[2]), "+f"(c[3])
        : "r"(a[0]), "r"(a[1]), "r"(a[2]), "r"(a[3]), "r"(b[0]), "r"(b[1]));
}

// ============================================================================
// Kernel 1: inv_deg[i] = 1/rowsum(A[i,:])   — pure read, 268 MB (~41 us)
// ============================================================================
__global__ void __launch_bounds__(256) rowsum_kernel(const float* __restrict__ A) {
    int row = blockIdx.x;
    const float4* r4 = reinterpret_cast<const float4*>(A + (size_t)row * NN);
    float s = 0.f;
#pragma unroll
    for (int it = 0; it < (NN / 4) / 256; it++) {
        float4 v = r4[it * 256 + threadIdx.x];
        s += (v.x + v.y) + (v.z + v.w);
    }
    __shared__ float red[256];
    red[threadIdx.x] = s;
    __syncthreads();
#pragma unroll
    for (int o = 128; o > 0; o >>= 1) {
        if (threadIdx.x < o) red[threadIdx.x] += red[threadIdx.x + o];
        __syncthreads();
    }
    if (threadIdx.x == 0) g_inv_deg[row] = 1.0f / red[0];
}

// ============================================================================
// Kernel 2: ysTh[d][j] = fp16( YSCALE * inv_deg[j] * (x @ W)[j][d] )
// ============================================================================
__global__ void __launch_bounds__(256) xw_kernel(const float* __restrict__ x,
                                                 const float* __restrict__ W) {
    __shared__ float xs[32][DF + 1];
    int r0 = blockIdx.x * 32;
    for (int idx = threadIdx.x; idx < 32 * DF; idx += 256) {
        int r = idx >> 8, c = idx & 255;
        xs[r][c] = x[(size_t)(r0 + r) * DF + c];
    }
    __syncthreads();

    int tx = threadIdx.x & 63;
    int ty = threadIdx.x >> 6;
    float acc[8][4];
#pragma unroll
    for (int r = 0; r < 8; r++)
#pragma unroll
        for (int c = 0; c < 4; c++) acc[r][c] = 0.f;

    const float4* W4 = reinterpret_cast<const float4*>(W);
#pragma unroll 4
    for (int k = 0; k < DF; k++) {
        float4 w = W4[k * 64 + tx];
        float xv[8];
#pragma unroll
        for (int r = 0; r < 8; r++) xv[r] = xs[ty * 8 + r][k];
#pragma unroll
        for (int r = 0; r < 8; r++) {
            acc[r][0] = fmaf(xv[r], w.x, acc[r][0]);
            acc[r][1] = fmaf(xv[r], w.y, acc[r][1]);
            acc[r][2] = fmaf(xv[r], w.z, acc[r][2]);
            acc[r][3] = fmaf(xv[r], w.w, acc[r][3]);
        }
    }
    __syncthreads();
#pragma unroll
    for (int r = 0; r < 8; r++)
#pragma unroll
        for (int c = 0; c < 4; c++) xs[ty * 8 + r][tx * 4 + c] = acc[r][c];
    __syncthreads();

    int d = threadIdx.x;
#pragma unroll
    for (int r = 0; r < 32; r += 4) {
        float s0 = g_inv_deg[r0 + r + 0] * YSCALE;
        float s1 = g_inv_deg[r0 + r + 1] * YSCALE;
        float s2 = g_inv_deg[r0 + r + 2] * YSCALE;
        float s3 = g_inv_deg[r0 + r + 3] * YSCALE;
        union { __half2 h[2]; uint2 u; } p;
        p.h[0] = __floats2half2_rn(xs[r + 0][d] * s0, xs[r + 1][d] * s1);
        p.h[1] = __floats2half2_rn(xs[r + 2][d] * s2, xs[r + 3][d] * s3);
        *reinterpret_cast<uint2*>(&g_ysTh[(size_t)d * NN + r0 + r]) = p.u;
    }
}

// ============================================================================
// Kernel 3: out = relu( (inv_deg_i/YSCALE) * (A @ Yh) + bias )
// A read as fp32 from gmem, converted to fp16 fragments in registers
// (LDS.64 + cvt.f16x2). B (Y) fp16 via ldmatrix. mma.sync m16n8k16.
// BM=128, BN=128, BK=64, 3-stage cp.async, 512 threads, warp grid 4x4.
// ============================================================================
constexpr int BM = 128, BN = 128, BK = 64;
constexpr int STAGES = 3;
constexpr int NK = NN / BK;                   // 128
constexpr int ROWA = (BK + 8) * 4;            // A row: 72 floats = 288 B (8g2+2t2 bank pattern)
constexpr int ROWB = (BK + 8) * 2;            // B row: 72 halves = 144 B (ldsm 4r pattern)
constexpr int A_TILE = BM * ROWA;             // 36864
constexpr int B_TILE = BN * ROWB;             // 18432
constexpr int STAGE_BYTES = A_TILE + B_TILE;  // 55296
constexpr int SMEM_GEMM = STAGES * STAGE_BYTES + 2 * BM * 4;  // 166912

__global__ void __launch_bounds__(512, 1) gcn_gemm_kernel(const float* __restrict__ A,
                                                          const float* __restrict__ bias,
                                                          float* __restrict__ out) {
    extern __shared__ char smem[];
    const uint32_t sbase = smem_u32(smem);
    float* invd_s = reinterpret_cast<float*>(smem + STAGES * STAGE_BYTES);
    float* bias_s = invd_s + BM;

    const int tid  = threadIdx.x;
    const int wid  = tid >> 5;
    const int lane = tid & 31;
    const int wm   = wid >> 2;          // 0..3 : 32-row slab
    const int wn   = wid & 3;           // 0..3 : 32-col slab
    const int mbase = blockIdx.x * BM;
    const int nbase = blockIdx.y * BN;

    if (tid < BM) {
        invd_s[tid] = g_inv_deg[mbase + tid] * (1.0f / YSCALE);
        bias_s[tid] = bias[nbase + tid];
    }

    const int g2 = lane >> 2, t2 = lane & 3;
    // A fragment base (fp32 in smem): row = wm*32 + g2, k-float = 2*t2
    const uint32_t abase = (uint32_t)((wm * 32 + g2) * ROWA + t2 * 8);
    // B ldmatrix offset (q = matrix index within x4)
    const int q = lane >> 3, r = lane & 7;
    const uint32_t boff = (uint32_t)((wn * 32 + (q >> 1) * 8 + r) * ROWB + (q & 1) * 16);

    // --- stage loader: A 2048 chunks (fp32) + B 1024 chunks (fp16), 16B each
    auto load_stage = [&](int st, int kt) {
        const uint32_t sA = sbase + st * STAGE_BYTES;
        const uint32_t sB = sA + A_TILE;
        const int k0 = kt * BK;
#pragma unroll
        for (int i = 0; i < 6; i++) {
            int c = i * 512 + tid;            // 0..3071
            if (c < 2048) {                   // A: 128 rows x 16 chunks
                int row = c >> 4, cq = c & 15;
                cp16(sA + row * ROWA + cq * 16,
                     A + (size_t)(mbase + row) * NN + k0 + cq * 4);
            } else {                          // B: 128 rows x 8 chunks
                int c2 = c - 2048;
                int row = c2 >> 3, cq = c2 & 7;
                cp16(sB + row * ROWB + cq * 16,
                     g_ysTh + (size_t)(nbase + row) * NN + k0 + cq * 8);
            }
        }
    };

    float acc[2][4][4];
#pragma unroll
    for (int mt = 0; mt < 2; mt++)
#pragma unroll
        for (int nt = 0; nt < 4; nt++)
#pragma unroll
            for (int i = 0; i < 4; i++) acc[mt][nt][i] = 0.f;

    // --- prologue: stages 0..1
    load_stage(0, 0); cp_commit();
    load_stage(1, 1); cp_commit();

    int st = 0;
    for (int kt = 0; kt < NK; kt++) {
        cp_wait<STAGES - 2>();
        __syncthreads();

        int pst = st + 2 >= STAGES ? st + 2 - STAGES : st + 2;
        if (kt + STAGES - 1 < NK) {
            load_stage(pst, kt + STAGES - 1);
        }
        cp_commit();

        const uint32_t sA = sbase + st * STAGE_BYTES;
        const uint32_t sB = sA + A_TILE;
#pragma unroll
        for (int ks = 0; ks < 4; ks++) {       // 4 x k16 steps
            uint32_t afr[2][4];
#pragma unroll
            for (int mt = 0; mt < 2; mt++) {
                const uint32_t ab = sA + abase + mt * (16 * ROWA) + ks * 64;
                afr[mt][0] = lds_cvt(ab);                 // (g2,   k0..1)
                afr[mt][1] = lds_cvt(ab + 8 * ROWA);      // (g2+8, k0..1)
                afr[mt][2] = lds_cvt(ab + 32);            // (g2,   k8..9)
                afr[mt][3] = lds_cvt(ab + 8 * ROWA + 32); // (g2+8, k8..9)
            }
            uint32_t bfr[2][4];
#pragma unroll
            for (int np = 0; np < 2; np++)
                ldsm4(bfr[np], sB + boff + np * (16 * ROWB) + ks * 32);
#pragma unroll
            for (int mt = 0; mt < 2; mt++)
#pragma unroll
                for (int nt = 0; nt < 4; nt++)
                    mma_f16(acc[mt][nt], afr[mt], &bfr[nt >> 1][(nt & 1) * 2]);
        }
        st = st + 1 >= STAGES ? 0 : st + 1;
    }

    // --- epilogue: scale by inv_deg(row)/YSCALE, add bias, relu, store float2
#pragma unroll
    for (int mt = 0; mt < 2; mt++) {
        const int rl = wm * 32 + mt * 16 + g2;        // local row
        const float s0 = invd_s[rl], s1 = invd_s[rl + 8];
        float* o0 = out + (size_t)(mbase + rl) * DF + nbase + wn * 32;
        float* o1 = o0 + (size_t)8 * DF;
#pragma unroll
        for (int nt = 0; nt < 4; nt++) {
            const int c = nt * 8 + t2 * 2;
            const float b0 = bias_s[wn * 32 + c], b1 = bias_s[wn * 32 + c + 1];
            float2 v0, v1;
            v0.x = fmaxf(fmaf(acc[mt][nt][0], s0, b0), 0.f);
            v0.y = fmaxf(fmaf(acc[mt][nt][1], s0, b1), 0.f);
            v1.x = fmaxf(fmaf(acc[mt][nt][2], s1, b0), 0.f);
            v1.y = fmaxf(fmaf(acc[mt][nt][3], s1, b1), 0.f);
            *reinterpret_cast<float2*>(o0 + c) = v0;
            *reinterpret_cast<float2*>(o1 + c) = v1;
        }
    }
}

// ============================================================================
// Launch
// ============================================================================
extern "C" void kernel_launch(void* const* d_in, const int* in_sizes, int n_in,
                              void* d_out, int out_size) {
    const float* x    = (const float*)d_in[0];   // [8192,256]
    const float* adj  = (const float*)d_in[1];   // [8192,8192]
    const float* W    = (const float*)d_in[2];   // [256,256]
    const float* bias = (const float*)d_in[3];   // [256]
    float* out = (float*)d_out;                  // [8192,256]

    cudaFuncSetAttribute(gcn_gemm_kernel, cudaFuncAttributeMaxDynamicSharedMemorySize,
                         SMEM_GEMM);

    rowsum_kernel<<<NN, 256>>>(adj);
    xw_kernel<<<NN / 32, 256>>>(x, W);
    dim3 grid(NN / BM, DF / BN);   // 64 x 2
    gcn_gemm_kernel<<<grid, 512, SMEM_GEMM>>>(adj, bias, out);
}

// round 6
// speedup vs baseline: 1.0451x; 1.0451x over previous
#include <cuda_runtime.h>
#include <cuda_fp16.h>
#include <cstdint>

#define DEV_INLINE __device__ __forceinline__

constexpr int NN = 8192;   // nodes
constexpr int DF = 256;    // feature dim
constexpr float YSCALE = 4096.f;   // exact pow2: keeps Y out of fp16 subnormals
constexpr int NSM = 148;           // persistent CTA count

// ---------------- intermediates (static device globals; no runtime alloc) ----
__device__ float  g_inv_deg[NN];
__device__ __half g_Ah[(size_t)NN * NN];     // fp16 copy of adjacency (rn)
__device__ __half g_ysTh[(size_t)DF * NN];   // [d][j] = fp16( YSCALE*inv_j*(xW)[j][d] )
__device__ float  g_part[NSM][2][128 * 128]; // per-CTA raw partial tiles

// ============================================================================
// helpers (baseline sm_103 ISA only: cp.async, ldmatrix, mma.sync)
// ============================================================================
DEV_INLINE uint32_t smem_u32(const void* p) {
    uint32_t a;
    asm("{ .reg .u64 t; cvta.to.shared.u64 t, %1; cvt.u32.u64 %0, t; }" : "=r"(a) : "l"(p));
    return a;
}
DEV_INLINE void cp16(uint32_t saddr, const void* g) {
    asm volatile("cp.async.cg.shared.global [%0], [%1], 16;" :: "r"(saddr), "l"(g));
}
DEV_INLINE void cp_commit() { asm volatile("cp.async.commit_group;"); }
template <int N> DEV_INLINE void cp_wait() { asm volatile("cp.async.wait_group %0;" :: "n"(N)); }

DEV_INLINE void ldsm4(uint32_t* d, uint32_t addr) {
    asm volatile("ldmatrix.sync.aligned.m8n8.x4.shared.b16 {%0,%1,%2,%3}, [%4];"
                 : "=r"(d[0]), "=r"(d[1]), "=r"(d[2]), "=r"(d[3]) : "r"(addr));
}
DEV_INLINE void mma_f16(float* c, const uint32_t* a, const uint32_t* b) {
    asm volatile(
        "mma.sync.aligned.m16n8k16.row.col.f32.f16.f16.f32 "
        "{%0,%1,%2,%3}, {%4,%5,%6,%7}, {%8,%9}, {%0,%1,%2,%3};"
        : "+f"(c[0]), "+f"(c[1]), "+f"(c[2]), "+f"(c[3])
        : "r"(a[0]), "r"(a[1]), "r"(a[2]), "r"(a[3]), "r"(b[0]), "r"(b[1]));
}

// span partition: CTA c owns global iters [start(c), start(c+1))
DEV_INLINE int span_start(int c) { return (c * 4096) / 37; }   // c*16384/148

// ============================================================================
// Kernel 1: inv_deg[i] = 1/rowsum(A[i,:]); also emits fp16 copy of A.
// 268 MB read + 134 MB write, HBM-bound (~54 us measured).
// ============================================================================
__global__ void __launch_bounds__(256) rowsum_kernel(const float* __restrict__ A) {
    int row = blockIdx.x;
    const float4* r4 = reinterpret_cast<const float4*>(A + (size_t)row * NN);
    __half* ah = g_Ah + (size_t)row * NN;
    float s = 0.f;
#pragma unroll
    for (int it = 0; it < (NN / 4) / 256; it++) {
        int idx = it * 256 + threadIdx.x;
        float4 v = r4[idx];
        s += (v.x + v.y) + (v.z + v.w);
        union { __half2 h[2]; uint2 u; } p;
        p.h[0] = __floats2half2_rn(v.x, v.y);
        p.h[1] = __floats2half2_rn(v.z, v.w);
        *reinterpret_cast<uint2*>(ah + (size_t)idx * 4) = p.u;
    }
    __shared__ float red[256];
    red[threadIdx.x] = s;
    __syncthreads();
#pragma unroll
    for (int o = 128; o > 0; o >>= 1) {
        if (threadIdx.x < o) red[threadIdx.x] += red[threadIdx.x + o];
        __syncthreads();
    }
    if (threadIdx.x == 0) g_inv_deg[row] = 1.0f / red[0];
}

// ============================================================================
// Kernel 2: ysTh[d][j] = fp16( YSCALE * inv_deg[j] * (x @ W)[j][d] )
// ============================================================================
__global__ void __launch_bounds__(256) xw_kernel(const float* __restrict__ x,
                                                 const float* __restrict__ W) {
    __shared__ float xs[32][DF + 1];
    int r0 = blockIdx.x * 32;
    for (int idx = threadIdx.x; idx < 32 * DF; idx += 256) {
        int r = idx >> 8, c = idx & 255;
        xs[r][c] = x[(size_t)(r0 + r) * DF + c];
    }
    __syncthreads();

    int tx = threadIdx.x & 63;
    int ty = threadIdx.x >> 6;
    float acc[8][4];
#pragma unroll
    for (int r = 0; r < 8; r++)
#pragma unroll
        for (int c = 0; c < 4; c++) acc[r][c] = 0.f;

    const float4* W4 = reinterpret_cast<const float4*>(W);
#pragma unroll 4
    for (int k = 0; k < DF; k++) {
        float4 w = W4[k * 64 + tx];
        float xv[8];
#pragma unroll
        for (int r = 0; r < 8; r++) xv[r] = xs[ty * 8 + r][k];
#pragma unroll
        for (int r = 0; r < 8; r++) {
            acc[r][0] = fmaf(xv[r], w.x, acc[r][0]);
            acc[r][1] = fmaf(xv[r], w.y, acc[r][1]);
            acc[r][2] = fmaf(xv[r], w.z, acc[r][2]);
            acc[r][3] = fmaf(xv[r], w.w, acc[r][3]);
        }
    }
    __syncthreads();
#pragma unroll
    for (int r = 0; r < 8; r++)
#pragma unroll
        for (int c = 0; c < 4; c++) xs[ty * 8 + r][tx * 4 + c] = acc[r][c];
    __syncthreads();

    int d = threadIdx.x;
#pragma unroll
    for (int r = 0; r < 32; r += 4) {
        float s0 = g_inv_deg[r0 + r + 0] * YSCALE;
        float s1 = g_inv_deg[r0 + r + 1] * YSCALE;
        float s2 = g_inv_deg[r0 + r + 2] * YSCALE;
        float s3 = g_inv_deg[r0 + r + 3] * YSCALE;
        union { __half2 h[2]; uint2 u; } p;
        p.h[0] = __floats2half2_rn(xs[r + 0][d] * s0, xs[r + 1][d] * s1);
        p.h[1] = __floats2half2_rn(xs[r + 2][d] * s2, xs[r + 3][d] * s3);
        *reinterpret_cast<uint2*>(&g_ysTh[(size_t)d * NN + r0 + r]) = p.u;
    }
}

// ============================================================================
// Kernel 3: persistent span GEMM — 148 CTAs, each owns ~111 global k-iters of
// the flattened (tile, k) space. Flushes raw fp32 partial tiles to g_part.
// BM=128, BN=128, BK=64, fp16 mma.sync, 3-stage cp.async, 512 threads.
// Iter space: gi in [0,16384): tile = gi>>7 (bx=tile>>1, by=tile&1), kit=gi&127.
// ============================================================================
constexpr int BK = 64;
constexpr int ROWH = (BK + 8) * 2;            // 144 B per 64-half row (padded)
constexpr int TILE_B = 128 * ROWH;            // 18432
constexpr int STAGE_B = 2 * TILE_B;           // 36864 (A + B)
constexpr int STAGES = 3;
constexpr int SMEM_GEMM = STAGES * STAGE_B;   // 110592

__global__ void __launch_bounds__(512, 1) gcn_gemm_kernel() {
    extern __shared__ char smem[];
    const uint32_t sbase = smem_u32(smem);

    const int tid  = threadIdx.x;
    const int wid  = tid >> 5;
    const int lane = tid & 31;
    const int wm   = wid >> 2;          // 0..3 : 32-row slab
    const int wn   = wid & 3;           // 0..3 : 32-col slab
    const int cta  = blockIdx.x;

    const int start = span_start(cta);
    const int end   = span_start(cta + 1);

    const int g2 = lane >> 2, t2 = lane & 3;
    const int q = lane >> 3, r = lane & 7;
    const uint32_t aoff = (uint32_t)((wm * 32 + (q & 1) * 8 + r) * ROWH + (q >> 1) * 16);
    const uint32_t boff = (uint32_t)((wn * 32 + (q >> 1) * 8 + r) * ROWH + (q & 1) * 16);

    // --- stage loader for global iter gi: A 1024 + B 1024 16B chunks
    auto load_stage = [&](int st, int gi) {
        const int tile = gi >> 7, kit = gi & 127;
        const int mb = (tile >> 1) * 128, nb = (tile & 1) * 128, k0 = kit * BK;
        const uint32_t sA = sbase + st * STAGE_B;
        const uint32_t sB = sA + TILE_B;
#pragma unroll
        for (int i = 0; i < 4; i++) {
            int c = i * 512 + tid;            // 0..2047
            if (c < 1024) {
                int row = c >> 3, cq = c & 7;
                cp16(sA + row * ROWH + cq * 16,
                     g_Ah + (size_t)(mb + row) * NN + k0 + cq * 8);
            } else {
                int c2 = c - 1024;
                int row = c2 >> 3, cq = c2 & 7;
                cp16(sB + row * ROWH + cq * 16,
                     g_ysTh + (size_t)(nb + row) * NN + k0 + cq * 8);
            }
        }
    };

    float acc[2][4][4];
#pragma unroll
    for (int mt = 0; mt < 2; mt++)
#pragma unroll
        for (int nt = 0; nt < 4; nt++)
#pragma unroll
            for (int i = 0; i < 4; i++) acc[mt][nt][i] = 0.f;

    // --- prologue (span length >= 110, so start+1 < end always)
    load_stage(0, start); cp_commit();
    load_stage(1, start + 1); cp_commit();

    int st = 0, seg = 0;
    for (int gi = start; gi < end; gi++) {
        cp_wait<1>();
        __syncthreads();

        int pst = st + 2 >= STAGES ? st + 2 - STAGES : st + 2;
        if (gi + 2 < end) load_stage(pst, gi + 2);
        cp_commit();

        const uint32_t sA = sbase + st * STAGE_B;
        const uint32_t sB = sA + TILE_B;
#pragma unroll
        for (int ks = 0; ks < 4; ks++) {       // 4 x k16 steps
            uint32_t afr[2][4];
#pragma unroll
            for (int mt = 0; mt < 2; mt++)
                ldsm4(afr[mt], sA + aoff + mt * (16 * ROWH) + ks * 32);
            uint32_t bfr[2][4];
#pragma unroll
            for (int np = 0; np < 2; np++)
                ldsm4(bfr[np], sB + boff + np * (16 * ROWH) + ks * 32);
#pragma unroll
            for (int mt = 0; mt < 2; mt++)
#pragma unroll
                for (int nt = 0; nt < 4; nt++)
                    mma_f16(acc[mt][nt], afr[mt], &bfr[nt >> 1][(nt & 1) * 2]);
        }

        // --- flush raw partial tile at tile boundary / span end
        if ((gi & 127) == 127 || gi == end - 1) {
            float* p = &g_part[cta][seg][0];
#pragma unroll
            for (int mt = 0; mt < 2; mt++) {
                const int rl = wm * 32 + mt * 16 + g2;
#pragma unroll
                for (int nt = 0; nt < 4; nt++) {
                    const int col = wn * 32 + nt * 8 + t2 * 2;
                    *reinterpret_cast<float2*>(p + rl * 128 + col) =
                        make_float2(acc[mt][nt][0], acc[mt][nt][1]);
                    *reinterpret_cast<float2*>(p + (rl + 8) * 128 + col) =
                        make_float2(acc[mt][nt][2], acc[mt][nt][3]);
#pragma unroll
                    for (int i = 0; i < 4; i++) acc[mt][nt][i] = 0.f;
                }
            }
            seg = 1;
        }
        st = st + 1 >= STAGES ? 0 : st + 1;
    }
}

// ============================================================================
// Kernel 4: per-tile reduction of 2-3 partial segments + epilogue
// out = relu( inv_deg_i/YSCALE * sum + bias ).  Grid = 128 tiles x 256 thr.
// ============================================================================
__global__ void __launch_bounds__(256) reduce_kernel(const float* __restrict__ bias,
                                                     float* __restrict__ out) {
    const int t  = blockIdx.x;                 // tile id 0..127
    const int mb = (t >> 1) * 128, nb = (t & 1) * 128;
    const int lo = t * 128, hi = lo + 127;     // iter range of this tile

    // conservative contributor range, filtered by exact overlap test
    int c_lo = (lo * NSM) >> 14; if (c_lo > 0) c_lo--;
    int c_hi = (hi * NSM) >> 14; if (c_hi < NSM - 1) c_hi++;

#pragma unroll 4
    for (int v = 0; v < 16; v++) {
        const int e = (v * 256 + threadIdx.x) * 4;
        const int row = e >> 7, col = e & 127;
        float4 s = make_float4(0.f, 0.f, 0.f, 0.f);
        for (int cc = c_lo; cc <= c_hi; cc++) {
            const int cs = span_start(cc), ce = span_start(cc + 1);
            if (cs > hi || ce <= lo) continue;            // no overlap
            const int sg = (t == (cs >> 7)) ? 0 : 1;
            const float4 p = *reinterpret_cast<const float4*>(&g_part[cc][sg][e]);
            s.x += p.x; s.y += p.y; s.z += p.z; s.w += p.w;
        }
        const float sinv = g_inv_deg[mb + row] * (1.0f / YSCALE);
        const float4 b = *reinterpret_cast<const float4*>(bias + nb + col);
        float4 o;
        o.x = fmaxf(fmaf(s.x, sinv, b.x), 0.f);
        o.y = fmaxf(fmaf(s.y, sinv, b.y), 0.f);
        o.z = fmaxf(fmaf(s.z, sinv, b.z), 0.f);
        o.w = fmaxf(fmaf(s.w, sinv, b.w), 0.f);
        *reinterpret_cast<float4*>(out + (size_t)(mb + row) * DF + nb + col) = o;
    }
}

// ============================================================================
// Launch
// ============================================================================
extern "C" void kernel_launch(void* const* d_in, const int* in_sizes, int n_in,
                              void* d_out, int out_size) {
    const float* x    = (const float*)d_in[0];   // [8192,256]
    const float* adj  = (const float*)d_in[1];   // [8192,8192]
    const float* W    = (const float*)d_in[2];   // [256,256]
    const float* bias = (const float*)d_in[3];   // [256]
    float* out = (float*)d_out;                  // [8192,256]

    cudaFuncSetAttribute(gcn_gemm_kernel, cudaFuncAttributeMaxDynamicSharedMemorySize,
                         SMEM_GEMM);

    rowsum_kernel<<<NN, 256>>>(adj);
    xw_kernel<<<NN / 32, 256>>>(x, W);
    gcn_gemm_kernel<<<NSM, 512, SMEM_GEMM>>>();
    reduce_kernel<<<128, 256>>>(bias, out);
}

// round 7
// speedup vs baseline: 1.0862x; 1.0394x over previous
#include <cuda_runtime.h>
#include <cuda_fp16.h>
#include <cstdint>

#define DEV_INLINE __device__ __forceinline__

constexpr int NN = 8192;   // nodes
constexpr int DF = 256;    // feature dim
constexpr float YSCALE = 4096.f;   // exact pow2: keeps Y out of fp16 subnormals
constexpr int NSM = 148;           // persistent CTA count

// ---------------- intermediates (static device globals; no runtime alloc) ----
__device__ float  g_inv_deg[NN];
__device__ __half g_Ah[(size_t)NN * NN];     // fp16 copy of adjacency (rn)
__device__ __half g_ysTh[(size_t)DF * NN];   // [d][j] = fp16( YSCALE*inv_j*(xW)[j][d] )
__device__ float  g_part[NSM][2][128 * 128]; // per-CTA raw partial tiles

// ============================================================================
// helpers (baseline sm_103 ISA only: cp.async, ldmatrix, mma.sync)
// ============================================================================
DEV_INLINE uint32_t smem_u32(const void* p) {
    uint32_t a;
    asm("{ .reg .u64 t; cvta.to.shared.u64 t, %1; cvt.u32.u64 %0, t; }" : "=r"(a) : "l"(p));
    return a;
}
DEV_INLINE void cp16(uint32_t saddr, const void* g) {
    asm volatile("cp.async.cg.shared.global [%0], [%1], 16;" :: "r"(saddr), "l"(g));
}
DEV_INLINE void cp_commit() { asm volatile("cp.async.commit_group;"); }
template <int N> DEV_INLINE void cp_wait() { asm volatile("cp.async.wait_group %0;" :: "n"(N)); }

DEV_INLINE void ldsm4(uint32_t* d, uint32_t addr) {
    asm volatile("ldmatrix.sync.aligned.m8n8.x4.shared.b16 {%0,%1,%2,%3}, [%4];"
                 : "=r"(d[0]), "=r"(d[1]), "=r"(d[2]), "=r"(d[3]) : "r"(addr));
}
DEV_INLINE void mma_f16(float* c, const uint32_t* a, const uint32_t* b) {
    asm volatile(
        "mma.sync.aligned.m16n8k16.row.col.f32.f16.f16.f32 "
        "{%0,%1,%2,%3}, {%4,%5,%6,%7}, {%8,%9}, {%0,%1,%2,%3};"
        : "+f"(c[0]), "+f"(c[1]), "+f"(c[2]), "+f"(c[3])
        : "r"(a[0]), "r"(a[1]), "r"(a[2]), "r"(a[3]), "r"(b[0]), "r"(b[1]));
}

// span partition: CTA c owns global iters [start(c), start(c+1))
DEV_INLINE int span_start(int c) { return (c * 4096) / 37; }   // c*16384/148

// ============================================================================
// Kernel 1: inv_deg[i] = 1/rowsum(A[i,:]); also emits fp16 copy of A.
// ============================================================================
__global__ void __launch_bounds__(256) rowsum_kernel(const float* __restrict__ A) {
    int row = blockIdx.x;
    const float4* r4 = reinterpret_cast<const float4*>(A + (size_t)row * NN);
    __half* ah = g_Ah + (size_t)row * NN;
    float s = 0.f;
#pragma unroll
    for (int it = 0; it < (NN / 4) / 256; it++) {
        int idx = it * 256 + threadIdx.x;
        float4 v = r4[idx];
        s += (v.x + v.y) + (v.z + v.w);
        union { __half2 h[2]; uint2 u; } p;
        p.h[0] = __floats2half2_rn(v.x, v.y);
        p.h[1] = __floats2half2_rn(v.z, v.w);
        *reinterpret_cast<uint2*>(ah + (size_t)idx * 4) = p.u;
    }
    __shared__ float red[256];
    red[threadIdx.x] = s;
    __syncthreads();
#pragma unroll
    for (int o = 128; o > 0; o >>= 1) {
        if (threadIdx.x < o) red[threadIdx.x] += red[threadIdx.x + o];
        __syncthreads();
    }
    if (threadIdx.x == 0) g_inv_deg[row] = 1.0f / red[0];
}

// ============================================================================
// Kernel 2: ysTh[d][j] = fp16( YSCALE * inv_deg[j] * (x @ W)[j][d] )
// ============================================================================
__global__ void __launch_bounds__(256) xw_kernel(const float* __restrict__ x,
                                                 const float* __restrict__ W) {
    __shared__ float xs[32][DF + 1];
    int r0 = blockIdx.x * 32;
    for (int idx = threadIdx.x; idx < 32 * DF; idx += 256) {
        int r = idx >> 8, c = idx & 255;
        xs[r][c] = x[(size_t)(r0 + r) * DF + c];
    }
    __syncthreads();

    int tx = threadIdx.x & 63;
    int ty = threadIdx.x >> 6;
    float acc[8][4];
#pragma unroll
    for (int r = 0; r < 8; r++)
#pragma unroll
        for (int c = 0; c < 4; c++) acc[r][c] = 0.f;

    const float4* W4 = reinterpret_cast<const float4*>(W);
#pragma unroll 4
    for (int k = 0; k < DF; k++) {
        float4 w = W4[k * 64 + tx];
        float xv[8];
#pragma unroll
        for (int r = 0; r < 8; r++) xv[r] = xs[ty * 8 + r][k];
#pragma unroll
        for (int r = 0; r < 8; r++) {
            acc[r][0] = fmaf(xv[r], w.x, acc[r][0]);
            acc[r][1] = fmaf(xv[r], w.y, acc[r][1]);
            acc[r][2] = fmaf(xv[r], w.z, acc[r][2]);
            acc[r][3] = fmaf(xv[r], w.w, acc[r][3]);
        }
    }
    __syncthreads();
#pragma unroll
    for (int r = 0; r < 8; r++)
#pragma unroll
        for (int c = 0; c < 4; c++) xs[ty * 8 + r][tx * 4 + c] = acc[r][c];
    __syncthreads();

    int d = threadIdx.x;
#pragma unroll
    for (int r = 0; r < 32; r += 4) {
        float s0 = g_inv_deg[r0 + r + 0] * YSCALE;
        float s1 = g_inv_deg[r0 + r + 1] * YSCALE;
        float s2 = g_inv_deg[r0 + r + 2] * YSCALE;
        float s3 = g_inv_deg[r0 + r + 3] * YSCALE;
        union { __half2 h[2]; uint2 u; } p;
        p.h[0] = __floats2half2_rn(xs[r + 0][d] * s0, xs[r + 1][d] * s1);
        p.h[1] = __floats2half2_rn(xs[r + 2][d] * s2, xs[r + 3][d] * s3);
        *reinterpret_cast<uint2*>(&g_ysTh[(size_t)d * NN + r0 + r]) = p.u;
    }
}

// ============================================================================
// Kernel 3: persistent span GEMM — 148 CTAs, ~111 global k-iters each.
// BM=128, BN=128, BK=64, fp16 mma.sync, 3-stage cp.async, 512 threads.
// Iter space: gi in [0,16384): tile = gi>>7 (bx=tile>>1, by=tile&1), kit=gi&127.
// ============================================================================
constexpr int BK = 64;
constexpr int ROWH = (BK + 8) * 2;            // 144 B per 64-half row (padded)
constexpr int TILE_B = 128 * ROWH;            // 18432
constexpr int STAGE_B = 2 * TILE_B;           // 36864 (A + B)
constexpr int STAGES = 3;
constexpr int SMEM_GEMM = STAGES * STAGE_B;   // 110592

__global__ void __launch_bounds__(512, 1) gcn_gemm_kernel() {
    extern __shared__ char smem[];
    const uint32_t sbase = smem_u32(smem);

    const int tid  = threadIdx.x;
    const int wid  = tid >> 5;
    const int lane = tid & 31;
    const int wm   = wid >> 2;          // 0..3 : 32-row slab
    const int wn   = wid & 3;           // 0..3 : 32-col slab
    const int cta  = blockIdx.x;

    const int start = span_start(cta);
    const int end   = span_start(cta + 1);

    const int g2 = lane >> 2, t2 = lane & 3;
    const int q = lane >> 3, r = lane & 7;
    const uint32_t aoff = (uint32_t)((wm * 32 + (q & 1) * 8 + r) * ROWH + (q >> 1) * 16);
    const uint32_t boff = (uint32_t)((wn * 32 + (q >> 1) * 8 + r) * ROWH + (q & 1) * 16);

    // --- stage loader for global iter gi: A 1024 + B 1024 16B chunks
    auto load_stage = [&](int st, int gi) {
        const int tile = gi >> 7, kit = gi & 127;
        const int mb = (tile >> 1) * 128, nb = (tile & 1) * 128, k0 = kit * BK;
        const uint32_t sA = sbase + st * STAGE_B;
        const uint32_t sB = sA + TILE_B;
#pragma unroll
        for (int i = 0; i < 4; i++) {
            int c = i * 512 + tid;            // 0..2047
            if (c < 1024) {
                int row = c >> 3, cq = c & 7;
                cp16(sA + row * ROWH + cq * 16,
                     g_Ah + (size_t)(mb + row) * NN + k0 + cq * 8);
            } else {
                int c2 = c - 1024;
                int row = c2 >> 3, cq = c2 & 7;
                cp16(sB + row * ROWH + cq * 16,
                     g_ysTh + (size_t)(nb + row) * NN + k0 + cq * 8);
            }
        }
    };

    float acc[2][4][4];
#pragma unroll
    for (int mt = 0; mt < 2; mt++)
#pragma unroll
        for (int nt = 0; nt < 4; nt++)
#pragma unroll
            for (int i = 0; i < 4; i++) acc[mt][nt][i] = 0.f;

    // --- prologue (span length >= 110, so start+1 < end always)
    load_stage(0, start); cp_commit();
    load_stage(1, start + 1); cp_commit();

    int st = 0, seg = 0;
    for (int gi = start; gi < end; gi++) {
        cp_wait<1>();
        __syncthreads();

        int pst = st + 2 >= STAGES ? st + 2 - STAGES : st + 2;
        if (gi + 2 < end) load_stage(pst, gi + 2);
        cp_commit();

        const uint32_t sA = sbase + st * STAGE_B;
        const uint32_t sB = sA + TILE_B;
#pragma unroll
        for (int ks = 0; ks < 4; ks++) {       // 4 x k16 steps
            uint32_t afr[2][4];
#pragma unroll
            for (int mt = 0; mt < 2; mt++)
                ldsm4(afr[mt], sA + aoff + mt * (16 * ROWH) + ks * 32);
            uint32_t bfr[2][4];
#pragma unroll
            for (int np = 0; np < 2; np++)
                ldsm4(bfr[np], sB + boff + np * (16 * ROWH) + ks * 32);
#pragma unroll
            for (int mt = 0; mt < 2; mt++)
#pragma unroll
                for (int nt = 0; nt < 4; nt++)
                    mma_f16(acc[mt][nt], afr[mt], &bfr[nt >> 1][(nt & 1) * 2]);
        }

        // --- flush raw partial tile at tile boundary / span end
        if ((gi & 127) == 127 || gi == end - 1) {
            float* p = &g_part[cta][seg][0];
#pragma unroll
            for (int mt = 0; mt < 2; mt++) {
                const int rl = wm * 32 + mt * 16 + g2;
#pragma unroll
                for (int nt = 0; nt < 4; nt++) {
                    const int col = wn * 32 + nt * 8 + t2 * 2;
                    *reinterpret_cast<float2*>(p + rl * 128 + col) =
                        make_float2(acc[mt][nt][0], acc[mt][nt][1]);
                    *reinterpret_cast<float2*>(p + (rl + 8) * 128 + col) =
                        make_float2(acc[mt][nt][2], acc[mt][nt][3]);
#pragma unroll
                    for (int i = 0; i < 4; i++) acc[mt][nt][i] = 0.f;
                }
            }
            seg = 1;
        }
        st = st + 1 >= STAGES ? 0 : st + 1;
    }
}

// ============================================================================
// Kernel 4: per-tile reduction of partial segments + epilogue.
// Grid = 128 tiles x 8 chunks = 1024 CTAs, 256 threads: each CTA sums its
// 2048-element slice over the <=4 contributing (cta,seg) pairs.
// out = relu( inv_deg_i/YSCALE * sum + bias ).
// ============================================================================
__global__ void __launch_bounds__(256) reduce_kernel(const float* __restrict__ bias,
                                                     float* __restrict__ out) {
    const int t     = blockIdx.x >> 3;         // tile id 0..127
    const int chunk = blockIdx.x & 7;          // 0..7 : 2048-elem slice
    const int mb = (t >> 1) * 128, nb = (t & 1) * 128;
    const int lo = t * 128, hi = lo + 127;     // iter range of this tile

    // resolve contributing segments once (<=4)
    const float* segp[4];
    int nseg = 0;
    int c_lo = (lo * NSM) >> 14; if (c_lo > 0) c_lo--;
    int c_hi = (hi * NSM) >> 14; if (c_hi < NSM - 1) c_hi++;
    for (int cc = c_lo; cc <= c_hi && nseg < 4; cc++) {
        const int cs = span_start(cc), ce = span_start(cc + 1);
        if (cs > hi || ce <= lo) continue;
        segp[nseg++] = &g_part[cc][(t == (cs >> 7)) ? 0 : 1][0];
    }

    const int e0 = chunk * 2048 + threadIdx.x * 8;   // two float4s per thread
#pragma unroll
    for (int v = 0; v < 2; v++) {
        const int e = e0 + v * 4;
        const int row = e >> 7, col = e & 127;
        float4 s = make_float4(0.f, 0.f, 0.f, 0.f);
#pragma unroll 4
        for (int g = 0; g < nseg; g++) {
            const float4 p = *reinterpret_cast<const float4*>(segp[g] + e);
            s.x += p.x; s.y += p.y; s.z += p.z; s.w += p.w;
        }
        const float sinv = g_inv_deg[mb + row] * (1.0f / YSCALE);
        const float4 b = *reinterpret_cast<const float4*>(bias + nb + col);
        float4 o;
        o.x = fmaxf(fmaf(s.x, sinv, b.x), 0.f);
        o.y = fmaxf(fmaf(s.y, sinv, b.y), 0.f);
        o.z = fmaxf(fmaf(s.z, sinv, b.z), 0.f);
        o.w = fmaxf(fmaf(s.w, sinv, b.w), 0.f);
        *reinterpret_cast<float4*>(out + (size_t)(mb + row) * DF + nb + col) = o;
    }
}

// ============================================================================
// Launch
// ============================================================================
extern "C" void kernel_launch(void* const* d_in, const int* in_sizes, int n_in,
                              void* d_out, int out_size) {
    const float* x    = (const float*)d_in[0];   // [8192,256]
    const float* adj  = (const float*)d_in[1];   // [8192,8192]
    const float* W    = (const float*)d_in[2];   // [256,256]
    const float* bias = (const float*)d_in[3];   // [256]
    float* out = (float*)d_out;                  // [8192,256]

    cudaFuncSetAttribute(gcn_gemm_kernel, cudaFuncAttributeMaxDynamicSharedMemorySize,
                         SMEM_GEMM);

    rowsum_kernel<<<NN, 256>>>(adj);
    xw_kernel<<<NN / 32, 256>>>(x, W);
    gcn_gemm_kernel<<<NSM, 512, SMEM_GEMM>>>();
    reduce_kernel<<<1024, 256>>>(bias, out);
}